// round 6
// baseline (speedup 1.0000x reference)
#include <cuda_runtime.h>
#include <cuda_fp16.h>

#define NB   8
#define NC   256
#define NH   96
#define NW   96
#define HW_  (NH * NW)          // 9216
#define CHW_ (NC * HW_)
#define NTOT (NB * CHW_)
#define TPB  128
#define NBLKX (NB * HW_ / TPB)  // 576 pixel blocks
#define CSPLIT 2
#define NCPB  (NC / CSPLIT)     // 128 channels per CTA

// Per channel: 9 corner quads, quad(yq,xb) = rows (yq,yq+1) x cols (xb,xb+1),
// packed as 2 x half2 (8 bytes) -> one LDS.64 per tap. All lanes of a warp
// read the same channel's 9 slots (72 B): distinct bank pairs, conflict-free.
struct H4 { __half2 lo, hi; };   // lo = (w[y][x], w[y][x+1]), hi = row y+1

__global__ __launch_bounds__(TPB)
void sdw_kernel(const float* __restrict__ x,
                const float* __restrict__ rot,
                const float* __restrict__ wgt,
                float* __restrict__ out)
{
    __shared__ __align__(8) H4 wq[NCPB * 9];

    const int tid = threadIdx.x;
    const int c0  = blockIdx.y * NCPB;

    // Build fp16 quads for this CTA's channel range: 128 ch * 9 quads = 1152.
    for (int i = tid; i < NCPB * 9; i += TPB) {
        int c = i / 9, q = i % 9;
        int yq = q / 3, xb = q % 3;
        const float* wc = wgt + (c0 + c) * 16;
        H4 v;
        v.lo = __floats2half2_rn(wc[yq * 4 + xb],     wc[yq * 4 + xb + 1]);
        v.hi = __floats2half2_rn(wc[yq * 4 + xb + 4], wc[yq * 4 + xb + 5]);
        wq[i] = v;
    }
    __syncthreads();

    const int blk = blockIdx.x;
    const int b   = blk / (HW_ / TPB);
    const int pix = (blk % (HW_ / TPB)) * TPB + tid;
    const int h = pix / NW, w = pix % NW;

    // Per-tap: 4 combined corner coefficients + one quad index.
    float c00[9], c01[9], c10[9], c11[9];
    int qo[9];

    const float* rbase = rot + (b * 18) * HW_ + pix;
    #pragma unroll
    for (int kh = 0; kh < 3; kh++) {
        #pragma unroll
        for (int kw = 0; kw < 3; kw++) {
            const int t = kh * 3 + kw;
            float ryv = __ldg(rbase + (2 * t) * HW_);
            float rxv = __ldg(rbase + (2 * t + 1) * HW_);
            float py = (kh + 0.5f) * (4.0f / 3.0f) - 0.5f + ryv;
            float px = (kw + 0.5f) * (4.0f / 3.0f) - 0.5f + rxv;
            float fpy = floorf(py), fpx = floorf(px);
            int iy = (int)fpy, ix = (int)fpx;
            float fy = py - fpy, fx = px - fpx;
            // Corner weights, zeroed when that corner lies outside the 4x4 scope.
            float ry0 = (iy >= 0  && iy < 4) ? (1.f - fy) : 0.f;   // row iy
            float ry1 = (iy >= -1 && iy < 3) ? fy         : 0.f;   // row iy+1
            float rx0 = (ix >= 0  && ix < 4) ? (1.f - fx) : 0.f;   // col ix
            float rx1 = (ix >= -1 && ix < 3) ? fx         : 0.f;   // col ix+1
            // Quad base + coefficient remap onto the quad's 2x2 footprint.
            int xb = min(max(ix, 0), 2);
            int dx = ix - xb;                      // -1/0/+1 in-range, else both 0
            float e0 = (dx == 0) ? rx0 : ((dx == -1) ? rx1 : 0.f);
            float e1 = (dx == 0) ? rx1 : ((dx ==  1) ? rx0 : 0.f);
            int yq = min(max(iy, 0), 2);
            int dy = iy - yq;
            float f0 = (dy == 0) ? ry0 : ((dy == -1) ? ry1 : 0.f);
            float f1 = (dy == 0) ? ry1 : ((dy ==  1) ? ry0 : 0.f);
            // Fold the zero-padding of x into the coefficients so inner-loop
            // x loads can be unconditional (loaded value irrelevant when 0).
            int hh = h + kh - 1, ww = w + kw - 1;
            float xval = (hh >= 0 && hh < NH && ww >= 0 && ww < NW) ? 1.f : 0.f;
            f0 *= xval; f1 *= xval;
            c00[t] = f0 * e0; c01[t] = f0 * e1;
            c10[t] = f1 * e0; c11[t] = f1 * e1;
            qo[t] = yq * 3 + xb;                   // quad slot 0..8
        }
    }

    const int off0 = b * CHW_ + c0 * HW_ + pix;
    // Only the first/last pixel block can form x addresses outside the buffer.
    const bool guard = (blk == 0) || (blk == NBLKX - 1);

    if (!guard) {
        const float* xp = x + off0;
        float* op = out + off0;
        const H4* cp = wq;
        #pragma unroll 2
        for (int c = 0; c < NCPB; ++c) {
            float acc = 0.f;
            #pragma unroll
            for (int kh = 0; kh < 3; kh++) {
                #pragma unroll
                for (int kw = 0; kw < 3; kw++) {
                    const int t = kh * 3 + kw;
                    H4 q = cp[qo[t]];
                    float2 lo = __half22float2(q.lo);
                    float2 hi = __half22float2(q.hi);
                    float g = c00[t] * lo.x + c01[t] * lo.y
                            + c10[t] * hi.x + c11[t] * hi.y;
                    float xv = __ldg(xp + (kh - 1) * NW + (kw - 1));
                    acc = fmaf(g, xv, acc);
                }
            }
            *op = acc;
            cp += 9; xp += HW_; op += HW_;
        }
    } else {
        float* op = out + off0;
        int off = off0;
        const H4* cp = wq;
        #pragma unroll 2
        for (int c = 0; c < NCPB; ++c) {
            float acc = 0.f;
            #pragma unroll
            for (int kh = 0; kh < 3; kh++) {
                #pragma unroll
                for (int kw = 0; kw < 3; kw++) {
                    const int t = kh * 3 + kw;
                    H4 q = cp[qo[t]];
                    float2 lo = __half22float2(q.lo);
                    float2 hi = __half22float2(q.hi);
                    float g = c00[t] * lo.x + c01[t] * lo.y
                            + c10[t] * hi.x + c11[t] * hi.y;
                    int o = off + (kh - 1) * NW + (kw - 1);
                    float xv = (o >= 0 && o < NTOT) ? x[o] : 0.f;
                    acc = fmaf(g, xv, acc);
                }
            }
            *op = acc;
            cp += 9; off += HW_; op += HW_;
        }
    }
}

extern "C" void kernel_launch(void* const* d_in, const int* in_sizes, int n_in,
                              void* d_out, int out_size)
{
    const float* x   = (const float*)d_in[0];
    const float* rot = (const float*)d_in[1];
    const float* wgt = (const float*)d_in[2];
    float* out = (float*)d_out;
    dim3 grid(NBLKX, CSPLIT);
    sdw_kernel<<<grid, TPB>>>(x, rot, wgt, out);
}